// round 1
// baseline (speedup 1.0000x reference)
#include <cuda_runtime.h>
#include <cuda_bf16.h>
#include <mma.h>

using namespace nvcuda;

#define B_ 4
#define S_ 2048
#define H_ 1024
#define E_ 8
#define K_ 512
#define F_ 4096

// ---------------- scratch (device globals: allocation-guard-safe) ----------
__device__ float g_scores[B_ * E_ * S_];          // softmax scores, [b,e,s]
__device__ int   g_idx[B_ * E_ * K_];             // top-K token indices
__device__ float g_gate[B_ * E_ * K_];            // top-K gate values
__device__ float g_h1[(size_t)B_ * E_ * K_ * F_]; // FFN hidden, 268 MB

// ---------------- kernel 1: gating logits + softmax ------------------------
// one warp per token; 8 dot products over H=1024, fp32 exact.
__global__ __launch_bounds__(256) void gate_kernel(const float* __restrict__ x,
                                                   const float* __restrict__ Wg) {
    int gwarp = (blockIdx.x * blockDim.x + threadIdx.x) >> 5;
    int lane = threadIdx.x & 31;
    if (gwarp >= B_ * S_) return;
    int b = gwarp / S_, s = gwarp % S_;
    const float* xr = x + ((size_t)b * S_ + s) * H_;

    float acc[E_];
#pragma unroll
    for (int e = 0; e < E_; e++) acc[e] = 0.f;
    for (int h = lane; h < H_; h += 32) {
        float xv = xr[h];
#pragma unroll
        for (int e = 0; e < E_; e++) acc[e] += xv * Wg[e * H_ + h];
    }
#pragma unroll
    for (int e = 0; e < E_; e++) {
#pragma unroll
        for (int o = 16; o > 0; o >>= 1)
            acc[e] += __shfl_xor_sync(0xffffffffu, acc[e], o);
    }
    float mx = acc[0];
#pragma unroll
    for (int e = 1; e < E_; e++) mx = fmaxf(mx, acc[e]);
    float den = 0.f;
#pragma unroll
    for (int e = 0; e < E_; e++) den += expf(acc[e] - mx);
    if (lane < E_) {
        float v = expf(acc[lane] - mx) / den;
        g_scores[((size_t)b * E_ + lane) * S_ + s] = v;
    }
}

// ---------------- kernel 2: top-K via bitonic sort --------------------------
// one block per (b,e); sort 2048 (val,idx) pairs; strict order:
// value descending, idx ascending (matches jax.lax.top_k tie-breaking).
__device__ __forceinline__ bool precedes(float va, int ia, float vb, int ib) {
    return (va > vb) || (va == vb && ia < ib);
}

__global__ __launch_bounds__(1024) void topk_kernel() {
    __shared__ float sv[S_];
    __shared__ int   si[S_];
    int be = blockIdx.x;
    int tid = threadIdx.x;
    for (int i = tid; i < S_; i += 1024) {
        sv[i] = g_scores[(size_t)be * S_ + i];
        si[i] = i;
    }
    __syncthreads();
    for (int k = 2; k <= S_; k <<= 1) {
        for (int j = k >> 1; j > 0; j >>= 1) {
            for (int i = tid; i < S_; i += 1024) {
                int ixj = i ^ j;
                if (ixj > i) {
                    float va = sv[i], vb = sv[ixj];
                    int ia = si[i], ib = si[ixj];
                    bool up = ((i & k) == 0);
                    bool swp = up ? precedes(vb, ib, va, ia)
                                  : precedes(va, ia, vb, ib);
                    if (swp) {
                        sv[i] = vb; sv[ixj] = va;
                        si[i] = ib; si[ixj] = ia;
                    }
                }
            }
            __syncthreads();
        }
    }
    for (int i = tid; i < K_; i += 1024) {
        g_idx[(size_t)be * K_ + i]  = si[i];
        g_gate[(size_t)be * K_ + i] = sv[i];
    }
}

// ---------------- GEMM config ----------------------------------------------
// BM=128, BN=64, BK=32; 256 threads = 8 warps in 4(M) x 2(N); warp tile 32x32.
#define LDA_S 36
#define LDB_S 68
#define LDC_S 68

// GELU tanh approximation (JAX default approximate=True)
__device__ __forceinline__ float gelu_tanh(float v) {
    float t = 0.7978845608028654f * (v + 0.044715f * v * v * v);
    return 0.5f * v * (1.f + tanhf(t));
}

// ---------------- kernel 3: FFN1 (gathered A) + bias + GELU ----------------
__global__ __launch_bounds__(256) void ffn1_kernel(const float* __restrict__ x,
                                                   const float* __restrict__ W1,
                                                   const float* __restrict__ b1) {
    __shared__ __align__(16) float smem[128 * LDC_S]; // 34816 B; unions C with A+B
    float* sA = smem;                 // [128][36]
    float* sB = smem + 128 * LDA_S;   // [32][68]

    const int e  = blockIdx.z;
    const int b  = blockIdx.y >> 2;
    const int mt = blockIdx.y & 3;
    const int n0 = blockIdx.x * 64;
    const int m0 = mt * 128;
    const int tid  = threadIdx.x;
    const int warp = tid >> 5;
    const int wm = warp & 3;
    const int wn = warp >> 2;

    const int be = b * E_ + e;
    const int* idxp = g_idx + (size_t)be * K_;
    const float* Wb = W1 + (size_t)e * H_ * F_;

    wmma::fragment<wmma::accumulator, 16, 16, 8, float> acc[2][2];
#pragma unroll
    for (int i = 0; i < 2; i++)
#pragma unroll
        for (int j = 0; j < 2; j++) wmma::fill_fragment(acc[i][j], 0.f);

    // per-thread gathered A row pointers (4 float4 loads per stage)
    const float* arow[4];
    int acol[4];
#pragma unroll
    for (int r = 0; r < 4; r++) {
        int l = tid + r * 256;
        int row = l >> 3;
        acol[r] = (l & 7) * 4;
        int token = idxp[m0 + row];
        arow[r] = x + ((size_t)b * S_ + token) * H_;
    }

    for (int k0 = 0; k0 < H_; k0 += 32) {
#pragma unroll
        for (int r = 0; r < 4; r++) {
            int l = tid + r * 256;
            int row = l >> 3;
            float4 v = *(const float4*)(arow[r] + k0 + acol[r]);
            *(float4*)(sA + row * LDA_S + acol[r]) = v;
        }
#pragma unroll
        for (int r = 0; r < 2; r++) {
            int l = tid + r * 256;
            int row = l >> 4;
            int c4 = (l & 15) * 4;
            float4 v = *(const float4*)(Wb + (size_t)(k0 + row) * F_ + n0 + c4);
            *(float4*)(sB + row * LDB_S + c4) = v;
        }
        __syncthreads();
#pragma unroll
        for (int kk = 0; kk < 32; kk += 8) {
            wmma::fragment<wmma::matrix_a, 16, 16, 8, wmma::precision::tf32, wmma::row_major> af[2];
            wmma::fragment<wmma::matrix_b, 16, 16, 8, wmma::precision::tf32, wmma::row_major> bf[2];
#pragma unroll
            for (int i = 0; i < 2; i++) {
                wmma::load_matrix_sync(af[i], sA + (wm * 32 + i * 16) * LDA_S + kk, LDA_S);
#pragma unroll
                for (int t = 0; t < af[i].num_elements; t++)
                    af[i].x[t] = wmma::__float_to_tf32(af[i].x[t]);
            }
#pragma unroll
            for (int j = 0; j < 2; j++) {
                wmma::load_matrix_sync(bf[j], sB + kk * LDB_S + wn * 32 + j * 16, LDB_S);
#pragma unroll
                for (int t = 0; t < bf[j].num_elements; t++)
                    bf[j].x[t] = wmma::__float_to_tf32(bf[j].x[t]);
            }
#pragma unroll
            for (int i = 0; i < 2; i++)
#pragma unroll
                for (int j = 0; j < 2; j++)
                    wmma::mma_sync(acc[i][j], af[i], bf[j], acc[i][j]);
        }
        __syncthreads();
    }

    // epilogue: stage C, add bias, GELU, store h1
#pragma unroll
    for (int i = 0; i < 2; i++)
#pragma unroll
        for (int j = 0; j < 2; j++)
            wmma::store_matrix_sync(smem + (wm * 32 + i * 16) * LDC_S + wn * 32 + j * 16,
                                    acc[i][j], LDC_S, wmma::mem_row_major);
    __syncthreads();
    const float* b1p = b1 + (size_t)e * F_ + n0;
    float* h1p = g_h1 + (((size_t)be * K_) + m0) * F_ + n0;
    for (int i = tid; i < 128 * 64; i += 256) {
        int r = i >> 6, c = i & 63;
        float v = smem[r * LDC_S + c] + b1p[c];
        h1p[(size_t)r * F_ + c] = gelu_tanh(v);
    }
}

// ---------------- kernel 4: FFN2 + bias + gate scale + scatter-add ---------
__global__ __launch_bounds__(256) void ffn2_kernel(const float* __restrict__ W2,
                                                   const float* __restrict__ b2,
                                                   float* __restrict__ out) {
    __shared__ __align__(16) float smem[128 * LDC_S];
    float* sA = smem;
    float* sB = smem + 128 * LDA_S;

    const int e  = blockIdx.z;
    const int b  = blockIdx.y >> 2;
    const int mt = blockIdx.y & 3;
    const int n0 = blockIdx.x * 64;
    const int m0 = mt * 128;
    const int tid  = threadIdx.x;
    const int warp = tid >> 5;
    const int wm = warp & 3;
    const int wn = warp >> 2;

    const int be = b * E_ + e;
    const float* Ab = g_h1 + ((size_t)be * K_ + m0) * F_;
    const float* Wb = W2 + (size_t)e * F_ * H_;

    wmma::fragment<wmma::accumulator, 16, 16, 8, float> acc[2][2];
#pragma unroll
    for (int i = 0; i < 2; i++)
#pragma unroll
        for (int j = 0; j < 2; j++) wmma::fill_fragment(acc[i][j], 0.f);

    for (int k0 = 0; k0 < F_; k0 += 32) {
#pragma unroll
        for (int r = 0; r < 4; r++) {
            int l = tid + r * 256;
            int row = l >> 3;
            int c4 = (l & 7) * 4;
            float4 v = *(const float4*)(Ab + (size_t)row * F_ + k0 + c4);
            *(float4*)(sA + row * LDA_S + c4) = v;
        }
#pragma unroll
        for (int r = 0; r < 2; r++) {
            int l = tid + r * 256;
            int row = l >> 4;
            int c4 = (l & 15) * 4;
            float4 v = *(const float4*)(Wb + (size_t)(k0 + row) * H_ + n0 + c4);
            *(float4*)(sB + row * LDB_S + c4) = v;
        }
        __syncthreads();
#pragma unroll
        for (int kk = 0; kk < 32; kk += 8) {
            wmma::fragment<wmma::matrix_a, 16, 16, 8, wmma::precision::tf32, wmma::row_major> af[2];
            wmma::fragment<wmma::matrix_b, 16, 16, 8, wmma::precision::tf32, wmma::row_major> bf[2];
#pragma unroll
            for (int i = 0; i < 2; i++) {
                wmma::load_matrix_sync(af[i], sA + (wm * 32 + i * 16) * LDA_S + kk, LDA_S);
#pragma unroll
                for (int t = 0; t < af[i].num_elements; t++)
                    af[i].x[t] = wmma::__float_to_tf32(af[i].x[t]);
            }
#pragma unroll
            for (int j = 0; j < 2; j++) {
                wmma::load_matrix_sync(bf[j], sB + kk * LDB_S + wn * 32 + j * 16, LDB_S);
#pragma unroll
                for (int t = 0; t < bf[j].num_elements; t++)
                    bf[j].x[t] = wmma::__float_to_tf32(bf[j].x[t]);
            }
#pragma unroll
            for (int i = 0; i < 2; i++)
#pragma unroll
                for (int j = 0; j < 2; j++)
                    wmma::mma_sync(acc[i][j], af[i], bf[j], acc[i][j]);
        }
        __syncthreads();
    }

#pragma unroll
    for (int i = 0; i < 2; i++)
#pragma unroll
        for (int j = 0; j < 2; j++)
            wmma::store_matrix_sync(smem + (wm * 32 + i * 16) * LDC_S + wn * 32 + j * 16,
                                    acc[i][j], LDC_S, wmma::mem_row_major);
    __syncthreads();

    const int*   idxp  = g_idx  + (size_t)be * K_;
    const float* gatep = g_gate + (size_t)be * K_;
    const float* b2p   = b2 + (size_t)e * H_ + n0;
    for (int i = tid; i < 128 * 64; i += 256) {
        int r = i >> 6, c = i & 63;
        float v = (smem[r * LDC_S + c] + b2p[c]) * gatep[m0 + r];
        int token = idxp[m0 + r];
        atomicAdd(&out[((size_t)b * S_ + token) * H_ + n0 + c], v);
    }
}

// ---------------- launch ----------------------------------------------------
extern "C" void kernel_launch(void* const* d_in, const int* in_sizes, int n_in,
                              void* d_out, int out_size) {
    const float* x  = (const float*)d_in[0];
    const float* Wg = (const float*)d_in[1];
    const float* W1 = (const float*)d_in[2];
    const float* b1 = (const float*)d_in[3];
    const float* W2 = (const float*)d_in[4];
    const float* b2 = (const float*)d_in[5];
    float* out = (float*)d_out;

    cudaMemsetAsync(out, 0, (size_t)B_ * S_ * H_ * sizeof(float), 0);
    gate_kernel<<<(B_ * S_) / 8, 256>>>(x, Wg);
    topk_kernel<<<B_ * E_, 1024>>>();
    ffn1_kernel<<<dim3(F_ / 64, (B_ * K_) / 128, E_), 256>>>(x, W1, b1);
    ffn2_kernel<<<dim3(H_ / 64, (B_ * K_) / 128, E_), 256>>>(W2, b2, out);
}

// round 2
// speedup vs baseline: 1.1609x; 1.1609x over previous
#include <cuda_runtime.h>
#include <cuda_bf16.h>
#include <mma.h>
#include <cstdint>

using namespace nvcuda;

#define B_ 4
#define S_ 2048
#define H_ 1024
#define E_ 8
#define K_ 512
#define F_ 4096

// GEMM tiling
#define BM 128
#define BN 128
#define BK 32
#define LDA 36   // floats, padded (144B rows, 16B aligned)
#define LDB 132  // floats, padded (528B rows, 16B aligned)
#define LDC 132
#define STAGE_FLOATS (BM * LDA + BK * LDB)   // 4608 + 4224 = 8832
#define SMEM_BYTES (3 * STAGE_FLOATS * 4)    // 105984 B

// ---------------- scratch (device globals: allocation-guard-safe) ----------
__device__ float g_scores[B_ * E_ * S_];
__device__ int   g_idx[B_ * E_ * K_];
__device__ float g_gate[B_ * E_ * K_];
__device__ float g_h1[(size_t)B_ * E_ * K_ * F_];   // 268 MB

// ---------------- cp.async helpers -----------------------------------------
__device__ __forceinline__ uint32_t smem_u32(const void* p) {
    return (uint32_t)__cvta_generic_to_shared(p);
}
#define CP_ASYNC16(dst_u32, src_ptr) \
    asm volatile("cp.async.cg.shared.global [%0], [%1], 16;\n" :: "r"(dst_u32), "l"(src_ptr))
#define CP_COMMIT() asm volatile("cp.async.commit_group;\n" ::)
#define CP_WAIT1()  asm volatile("cp.async.wait_group 1;\n" ::)

// ---------------- kernel 1: gating logits + softmax ------------------------
__global__ __launch_bounds__(256) void gate_kernel(const float* __restrict__ x,
                                                   const float* __restrict__ Wg) {
    int gwarp = (blockIdx.x * blockDim.x + threadIdx.x) >> 5;
    int lane = threadIdx.x & 31;
    if (gwarp >= B_ * S_) return;
    int b = gwarp / S_, s = gwarp % S_;
    const float* xr = x + ((size_t)b * S_ + s) * H_;

    float acc[E_];
#pragma unroll
    for (int e = 0; e < E_; e++) acc[e] = 0.f;
    for (int h = lane; h < H_; h += 32) {
        float xv = xr[h];
#pragma unroll
        for (int e = 0; e < E_; e++) acc[e] += xv * Wg[e * H_ + h];
    }
#pragma unroll
    for (int e = 0; e < E_; e++) {
#pragma unroll
        for (int o = 16; o > 0; o >>= 1)
            acc[e] += __shfl_xor_sync(0xffffffffu, acc[e], o);
    }
    float mx = acc[0];
#pragma unroll
    for (int e = 1; e < E_; e++) mx = fmaxf(mx, acc[e]);
    float den = 0.f;
#pragma unroll
    for (int e = 0; e < E_; e++) den += expf(acc[e] - mx);
    if (lane < E_) {
        float v = expf(acc[lane] - mx) / den;
        g_scores[((size_t)b * E_ + lane) * S_ + s] = v;
    }
}

// ---------------- kernel 2: top-K via bitonic sort --------------------------
__device__ __forceinline__ bool precedes(float va, int ia, float vb, int ib) {
    return (va > vb) || (va == vb && ia < ib);
}

__global__ __launch_bounds__(1024) void topk_kernel() {
    __shared__ float sv[S_];
    __shared__ int   si[S_];
    int be = blockIdx.x;
    int tid = threadIdx.x;
    for (int i = tid; i < S_; i += 1024) {
        sv[i] = g_scores[(size_t)be * S_ + i];
        si[i] = i;
    }
    __syncthreads();
    for (int k = 2; k <= S_; k <<= 1) {
        for (int j = k >> 1; j > 0; j >>= 1) {
            for (int i = tid; i < S_; i += 1024) {
                int ixj = i ^ j;
                if (ixj > i) {
                    float va = sv[i], vb = sv[ixj];
                    int ia = si[i], ib = si[ixj];
                    bool up = ((i & k) == 0);
                    bool swp = up ? precedes(vb, ib, va, ia)
                                  : precedes(va, ia, vb, ib);
                    if (swp) {
                        sv[i] = vb; sv[ixj] = va;
                        si[i] = ib; si[ixj] = ia;
                    }
                }
            }
            __syncthreads();
        }
    }
    for (int i = tid; i < K_; i += 1024) {
        g_idx[(size_t)be * K_ + i]  = si[i];
        g_gate[(size_t)be * K_ + i] = sv[i];
    }
}

// GELU tanh approximation (JAX default approximate=True)
__device__ __forceinline__ float gelu_tanh(float v) {
    float t = 0.7978845608028654f * (v + 0.044715f * v * v * v);
    return 0.5f * v * (1.f + tanhf(t));
}

// ---------------- kernel 3: FFN1 (gathered A) + bias + GELU ----------------
// C[128x128] = gather(x)[128xH] @ W1[e][HxF] tile; 3-stage cp.async pipeline.
__global__ __launch_bounds__(256, 2) void ffn1_kernel(const float* __restrict__ x,
                                                      const float* __restrict__ W1,
                                                      const float* __restrict__ b1) {
    extern __shared__ __align__(16) float smem[];

    const int e  = blockIdx.z;
    const int b  = blockIdx.y >> 2;
    const int mt = blockIdx.y & 3;
    const int n0 = blockIdx.x * BN;
    const int m0 = mt * BM;
    const int tid  = threadIdx.x;
    const int warp = tid >> 5;
    const int wm = warp & 3;     // 4 warps in M
    const int wn = warp >> 2;    // 2 warps in N

    const int be = b * E_ + e;
    const int* idxp = g_idx + (size_t)be * K_;
    const float* Wb = W1 + (size_t)e * H_ * F_;

    // gathered A row pointers (row = (tid + r*256) >> 3)
    const float* arow[4];
    int acol[4];
#pragma unroll
    for (int r = 0; r < 4; r++) {
        int c = tid + r * 256;
        int row = c >> 3;
        acol[r] = (c & 7) * 4;
        arow[r] = x + ((size_t)b * S_ + idxp[m0 + row]) * H_;
    }

    auto issue = [&](int k0, int stg) {
        float* sA = smem + stg * STAGE_FLOATS;
        float* sB = sA + BM * LDA;
#pragma unroll
        for (int r = 0; r < 4; r++) {
            int c = tid + r * 256;
            int row = c >> 3;
            CP_ASYNC16(smem_u32(sA + row * LDA + acol[r]), arow[r] + k0 + acol[r]);
        }
#pragma unroll
        for (int r = 0; r < 4; r++) {
            int c = tid + r * 256;
            int row = c >> 5;
            int col = (c & 31) * 4;
            CP_ASYNC16(smem_u32(sB + row * LDB + col),
                       Wb + (size_t)(k0 + row) * F_ + n0 + col);
        }
    };

    wmma::fragment<wmma::accumulator, 16, 16, 8, float> acc[2][4];
#pragma unroll
    for (int i = 0; i < 2; i++)
#pragma unroll
        for (int j = 0; j < 4; j++) wmma::fill_fragment(acc[i][j], 0.f);

    const int ITERS = H_ / BK;    // 32
    issue(0, 0); CP_COMMIT();
    issue(BK, 1); CP_COMMIT();
    int buf = 0;
    for (int it = 0; it < ITERS; it++) {
        CP_WAIT1();
        __syncthreads();
        if (it + 2 < ITERS) issue((it + 2) * BK, (buf + 2) % 3);
        CP_COMMIT();
        float* sA = smem + buf * STAGE_FLOATS;
        float* sB = sA + BM * LDA;
#pragma unroll
        for (int kk = 0; kk < BK; kk += 8) {
            wmma::fragment<wmma::matrix_a, 16, 16, 8, wmma::precision::tf32, wmma::row_major> af[2];
            wmma::fragment<wmma::matrix_b, 16, 16, 8, wmma::precision::tf32, wmma::row_major> bf[4];
#pragma unroll
            for (int i = 0; i < 2; i++) {
                wmma::load_matrix_sync(af[i], sA + (wm * 32 + i * 16) * LDA + kk, LDA);
#pragma unroll
                for (int t = 0; t < af[i].num_elements; t++)
                    af[i].x[t] = wmma::__float_to_tf32(af[i].x[t]);
            }
#pragma unroll
            for (int j = 0; j < 4; j++) {
                wmma::load_matrix_sync(bf[j], sB + kk * LDB + wn * 64 + j * 16, LDB);
#pragma unroll
                for (int t = 0; t < bf[j].num_elements; t++)
                    bf[j].x[t] = wmma::__float_to_tf32(bf[j].x[t]);
            }
#pragma unroll
            for (int i = 0; i < 2; i++)
#pragma unroll
                for (int j = 0; j < 4; j++)
                    wmma::mma_sync(acc[i][j], af[i], bf[j], acc[i][j]);
        }
        buf = (buf == 2) ? 0 : buf + 1;
    }
    __syncthreads();

    // epilogue: stage C in smem, bias + GELU, write h1
#pragma unroll
    for (int i = 0; i < 2; i++)
#pragma unroll
        for (int j = 0; j < 4; j++)
            wmma::store_matrix_sync(smem + (wm * 32 + i * 16) * LDC + wn * 64 + j * 16,
                                    acc[i][j], LDC, wmma::mem_row_major);
    __syncthreads();
    const float* b1p = b1 + (size_t)e * F_ + n0;
    float* h1p = g_h1 + (((size_t)be * K_) + m0) * F_ + n0;
#pragma unroll
    for (int r = 0; r < 16; r++) {
        int c = tid + r * 256;
        int row = c >> 5;
        int col = (c & 31) * 4;
        float4 v = *(const float4*)(smem + row * LDC + col);
        float4 bb = *(const float4*)(b1p + col);
        v.x = gelu_tanh(v.x + bb.x);
        v.y = gelu_tanh(v.y + bb.y);
        v.z = gelu_tanh(v.z + bb.z);
        v.w = gelu_tanh(v.w + bb.w);
        *(float4*)(h1p + (size_t)row * F_ + col) = v;
    }
}

// ---------------- kernel 4: FFN2 + bias + gate scale + scatter-add ---------
__global__ __launch_bounds__(256, 2) void ffn2_kernel(const float* __restrict__ W2,
                                                      const float* __restrict__ b2,
                                                      float* __restrict__ out) {
    extern __shared__ __align__(16) float smem[];

    const int e  = blockIdx.z;
    const int b  = blockIdx.y >> 2;
    const int mt = blockIdx.y & 3;
    const int n0 = blockIdx.x * BN;
    const int m0 = mt * BM;
    const int tid  = threadIdx.x;
    const int warp = tid >> 5;
    const int wm = warp & 3;
    const int wn = warp >> 2;

    const int be = b * E_ + e;
    const float* Ab = g_h1 + ((size_t)be * K_ + m0) * F_;
    const float* Wb = W2 + (size_t)e * F_ * H_;

    auto issue = [&](int k0, int stg) {
        float* sA = smem + stg * STAGE_FLOATS;
        float* sB = sA + BM * LDA;
#pragma unroll
        for (int r = 0; r < 4; r++) {
            int c = tid + r * 256;
            int row = c >> 3;
            int col = (c & 7) * 4;
            CP_ASYNC16(smem_u32(sA + row * LDA + col),
                       Ab + (size_t)row * F_ + k0 + col);
        }
#pragma unroll
        for (int r = 0; r < 4; r++) {
            int c = tid + r * 256;
            int row = c >> 5;
            int col = (c & 31) * 4;
            CP_ASYNC16(smem_u32(sB + row * LDB + col),
                       Wb + (size_t)(k0 + row) * H_ + n0 + col);
        }
    };

    wmma::fragment<wmma::accumulator, 16, 16, 8, float> acc[2][4];
#pragma unroll
    for (int i = 0; i < 2; i++)
#pragma unroll
        for (int j = 0; j < 4; j++) wmma::fill_fragment(acc[i][j], 0.f);

    const int ITERS = F_ / BK;    // 128
    issue(0, 0); CP_COMMIT();
    issue(BK, 1); CP_COMMIT();
    int buf = 0;
    for (int it = 0; it < ITERS; it++) {
        CP_WAIT1();
        __syncthreads();
        if (it + 2 < ITERS) issue((it + 2) * BK, (buf + 2) % 3);
        CP_COMMIT();
        float* sA = smem + buf * STAGE_FLOATS;
        float* sB = sA + BM * LDA;
#pragma unroll
        for (int kk = 0; kk < BK; kk += 8) {
            wmma::fragment<wmma::matrix_a, 16, 16, 8, wmma::precision::tf32, wmma::row_major> af[2];
            wmma::fragment<wmma::matrix_b, 16, 16, 8, wmma::precision::tf32, wmma::row_major> bf[4];
#pragma unroll
            for (int i = 0; i < 2; i++) {
                wmma::load_matrix_sync(af[i], sA + (wm * 32 + i * 16) * LDA + kk, LDA);
#pragma unroll
                for (int t = 0; t < af[i].num_elements; t++)
                    af[i].x[t] = wmma::__float_to_tf32(af[i].x[t]);
            }
#pragma unroll
            for (int j = 0; j < 4; j++) {
                wmma::load_matrix_sync(bf[j], sB + kk * LDB + wn * 64 + j * 16, LDB);
#pragma unroll
                for (int t = 0; t < bf[j].num_elements; t++)
                    bf[j].x[t] = wmma::__float_to_tf32(bf[j].x[t]);
            }
#pragma unroll
            for (int i = 0; i < 2; i++)
#pragma unroll
                for (int j = 0; j < 4; j++)
                    wmma::mma_sync(acc[i][j], af[i], bf[j], acc[i][j]);
        }
        buf = (buf == 2) ? 0 : buf + 1;
    }
    __syncthreads();

#pragma unroll
    for (int i = 0; i < 2; i++)
#pragma unroll
        for (int j = 0; j < 4; j++)
            wmma::store_matrix_sync(smem + (wm * 32 + i * 16) * LDC + wn * 64 + j * 16,
                                    acc[i][j], LDC, wmma::mem_row_major);
    __syncthreads();

    const int*   idxp  = g_idx  + (size_t)be * K_;
    const float* gatep = g_gate + (size_t)be * K_;
    const float* b2p   = b2 + (size_t)e * H_ + n0;
#pragma unroll
    for (int r = 0; r < 16; r++) {
        int c = tid + r * 256;
        int row = c >> 5;
        int col = (c & 31) * 4;
        float4 v = *(const float4*)(smem + row * LDC + col);
        float4 bb = *(const float4*)(b2p + col);
        float gsc = gatep[m0 + row];
        int token = idxp[m0 + row];
        float* op = out + ((size_t)b * S_ + token) * H_ + n0 + col;
        atomicAdd(op + 0, (v.x + bb.x) * gsc);
        atomicAdd(op + 1, (v.y + bb.y) * gsc);
        atomicAdd(op + 2, (v.z + bb.z) * gsc);
        atomicAdd(op + 3, (v.w + bb.w) * gsc);
    }
}

// ---------------- launch ----------------------------------------------------
extern "C" void kernel_launch(void* const* d_in, const int* in_sizes, int n_in,
                              void* d_out, int out_size) {
    const float* x  = (const float*)d_in[0];
    const float* Wg = (const float*)d_in[1];
    const float* W1 = (const float*)d_in[2];
    const float* b1 = (const float*)d_in[3];
    const float* W2 = (const float*)d_in[4];
    const float* b2 = (const float*)d_in[5];
    float* out = (float*)d_out;

    static int smem_set = 0;
    if (!smem_set) {
        cudaFuncSetAttribute(ffn1_kernel, cudaFuncAttributeMaxDynamicSharedMemorySize, SMEM_BYTES);
        cudaFuncSetAttribute(ffn2_kernel, cudaFuncAttributeMaxDynamicSharedMemorySize, SMEM_BYTES);
        smem_set = 1;
    }

    cudaMemsetAsync(out, 0, (size_t)B_ * S_ * H_ * sizeof(float), 0);
    gate_kernel<<<(B_ * S_) / 8, 256>>>(x, Wg);
    topk_kernel<<<B_ * E_, 1024>>>();
    ffn1_kernel<<<dim3(F_ / BN, (B_ * K_) / BM, E_), 256, SMEM_BYTES>>>(x, W1, b1);
    ffn2_kernel<<<dim3(H_ / BN, (B_ * K_) / BM, E_), 256, SMEM_BYTES>>>(W2, b2, out);
}

// round 4
// speedup vs baseline: 4.5465x; 3.9164x over previous
#include <cuda_runtime.h>
#include <cuda_fp16.h>
#include <mma.h>
#include <cstdint>

using namespace nvcuda;

#define B_ 4
#define S_ 2048
#define H_ 1024
#define E_ 8
#define K_ 512
#define F_ 4096

// GEMM tiling (half inputs, fp32 accum)
#define BM 128
#define BN 128
#define BK 32
#define LDA_H 40    // halves; 80B row stride (multiple of 16B)
#define LDB_H 136   // halves; 272B row stride (multiple of 16B)
#define LDC 132
#define NSTAGE 4
#define STAGE_HALVES (BM * LDA_H + BK * LDB_H)     // 5120 + 4352 = 9472
#define STAGE_BYTES (STAGE_HALVES * 2)             // 18944
#define SMEM_BYTES (NSTAGE * STAGE_BYTES)          // 75776 (> C tile 67584)

// ---------------- scratch (device globals: allocation-guard-safe) ----------
__device__ float  g_scores[B_ * E_ * S_];
__device__ int    g_idx[B_ * E_ * K_];
__device__ float  g_gate[B_ * E_ * K_];
__device__ __half g_xgh[(size_t)B_ * E_ * K_ * H_];   // gathered tokens (half)
__device__ __half g_h1h[(size_t)B_ * E_ * K_ * F_];   // hidden (half), 134 MB
__device__ __half g_w1h[(size_t)E_ * H_ * F_];        // W1 as half, [E][H][F]
__device__ __half g_w2h[(size_t)E_ * F_ * H_];        // W2 as half, [E][F][H]

// ---------------- cp.async helpers -----------------------------------------
__device__ __forceinline__ uint32_t smem_u32(const void* p) {
    return (uint32_t)__cvta_generic_to_shared(p);
}
#define CP_ASYNC16(dst_u32, src_ptr) \
    asm volatile("cp.async.cg.shared.global [%0], [%1], 16;\n" :: "r"(dst_u32), "l"(src_ptr))
#define CP_COMMIT() asm volatile("cp.async.commit_group;\n" ::)
#define CP_WAIT2()  asm volatile("cp.async.wait_group 2;\n" ::)

// ---------------- kernel 1: gating + softmax -------------------------------
__global__ __launch_bounds__(256) void gate_kernel(const float* __restrict__ x,
                                                   const float* __restrict__ Wg) {
    int gwarp = (blockIdx.x * blockDim.x + threadIdx.x) >> 5;
    int lane = threadIdx.x & 31;
    if (gwarp >= B_ * S_) return;
    int b = gwarp / S_, s = gwarp % S_;
    const float* xr = x + ((size_t)b * S_ + s) * H_;

    float acc[E_];
#pragma unroll
    for (int e = 0; e < E_; e++) acc[e] = 0.f;
    for (int h = lane; h < H_; h += 32) {
        float xv = xr[h];
#pragma unroll
        for (int e = 0; e < E_; e++) acc[e] += xv * Wg[e * H_ + h];
    }
#pragma unroll
    for (int e = 0; e < E_; e++) {
#pragma unroll
        for (int o = 16; o > 0; o >>= 1)
            acc[e] += __shfl_xor_sync(0xffffffffu, acc[e], o);
    }
    float mx = acc[0];
#pragma unroll
    for (int e = 1; e < E_; e++) mx = fmaxf(mx, acc[e]);
    float den = 0.f;
#pragma unroll
    for (int e = 0; e < E_; e++) den += expf(acc[e] - mx);
    if (lane < E_) {
        g_scores[((size_t)b * E_ + lane) * S_ + s] = expf(acc[lane] - mx) / den;
    }
}

// ---------------- kernel 2: top-K (bitonic, jax.lax.top_k tie order) -------
__device__ __forceinline__ bool precedes(float va, int ia, float vb, int ib) {
    return (va > vb) || (va == vb && ia < ib);
}

__global__ __launch_bounds__(1024) void topk_kernel() {
    __shared__ float sv[S_];
    __shared__ int   si[S_];
    int be = blockIdx.x;
    int tid = threadIdx.x;
    for (int i = tid; i < S_; i += 1024) {
        sv[i] = g_scores[(size_t)be * S_ + i];
        si[i] = i;
    }
    __syncthreads();
    for (int k = 2; k <= S_; k <<= 1) {
        for (int j = k >> 1; j > 0; j >>= 1) {
            for (int i = tid; i < S_; i += 1024) {
                int ixj = i ^ j;
                if (ixj > i) {
                    float va = sv[i], vb = sv[ixj];
                    int ia = si[i], ib = si[ixj];
                    bool up = ((i & k) == 0);
                    bool swp = up ? precedes(vb, ib, va, ia)
                                  : precedes(va, ia, vb, ib);
                    if (swp) {
                        sv[i] = vb; sv[ixj] = va;
                        si[i] = ib; si[ixj] = ia;
                    }
                }
            }
            __syncthreads();
        }
    }
    for (int i = tid; i < K_; i += 1024) {
        g_idx[(size_t)be * K_ + i]  = si[i];
        g_gate[(size_t)be * K_ + i] = sv[i];
    }
}

// ---------------- kernel 2b: gather chosen tokens -> half ------------------
__global__ __launch_bounds__(256) void gather_kernel(const float* __restrict__ x) {
    int row = blockIdx.x;                 // 0..B*E*K-1
    int be = row / K_;
    int b = be / E_;
    int token = g_idx[row];
    const float4* src = (const float4*)(x + ((size_t)b * S_ + token) * H_);
    __half2* dst = (__half2*)(g_xgh + (size_t)row * H_);
    float4 v = src[threadIdx.x];
    dst[threadIdx.x * 2 + 0] = __floats2half2_rn(v.x, v.y);
    dst[threadIdx.x * 2 + 1] = __floats2half2_rn(v.z, v.w);
}

// ---------------- kernel 2c: fp32 -> fp16 convert (layout preserved) -------
__global__ __launch_bounds__(256) void convert_kernel(const float* __restrict__ src,
                                                      __half* __restrict__ dst) {
    size_t i = ((size_t)blockIdx.x * 256 + threadIdx.x) * 4;
    float4 v = *(const float4*)(src + i);
    __half2* d = (__half2*)(dst + i);
    d[0] = __floats2half2_rn(v.x, v.y);
    d[1] = __floats2half2_rn(v.z, v.w);
}

// GELU tanh approximation (JAX default approximate=True)
__device__ __forceinline__ float gelu_tanh(float v) {
    float t = 0.7978845608028654f * (v + 0.044715f * v * v * v);
    return 0.5f * v * (1.f + tanhf(t));
}

// ---------------- shared GEMM mainloop (half WMMA, fp32 accum) -------------
// C[BMxBN] = A[BM x iters*BK] @ B[iters*BK x N](row-major slice at n0)
// 4-stage cp.async ring. 8 warps: 4(M) x 2(N), warp tile 32x64.
struct AccTile {
    wmma::fragment<wmma::accumulator, 16, 16, 16, float> a[2][4];
};

__device__ __forceinline__ void gemm_half(const __half* __restrict__ A, size_t lda,
                                          const __half* __restrict__ Bg, size_t ldb,
                                          int n0, int iters, __half* sbase,
                                          AccTile& acc, int tid) {
    const int warp = tid >> 5;
    const int wm = warp & 3;
    const int wn = warp >> 2;

    auto issue = [&](int j) {
        __half* st = sbase + (j % NSTAGE) * STAGE_HALVES;
        __half* stB = st + BM * LDA_H;
        int k0 = j * BK;
#pragma unroll
        for (int r = 0; r < 2; r++) {
            int g = tid + r * 256;           // 0..511
            int row = g >> 2, c = (g & 3) * 8;
            CP_ASYNC16(smem_u32(st + row * LDA_H + c), A + (size_t)row * lda + k0 + c);
        }
#pragma unroll
        for (int r = 0; r < 2; r++) {
            int g = tid + r * 256;
            int row = g >> 4, c = (g & 15) * 8;
            CP_ASYNC16(smem_u32(stB + row * LDB_H + c),
                       Bg + (size_t)(k0 + row) * ldb + n0 + c);
        }
    };

    issue(0); CP_COMMIT();
    issue(1); CP_COMMIT();
    issue(2); CP_COMMIT();
    for (int j = 0; j < iters; j++) {
        CP_WAIT2();
        __syncthreads();
        if (j + 3 < iters) issue(j + 3);
        CP_COMMIT();
        __half* st = sbase + (j % NSTAGE) * STAGE_HALVES;
        __half* stB = st + BM * LDA_H;
#pragma unroll
        for (int kk = 0; kk < BK; kk += 16) {
            wmma::fragment<wmma::matrix_a, 16, 16, 16, __half, wmma::row_major> af[2];
            wmma::fragment<wmma::matrix_b, 16, 16, 16, __half, wmma::row_major> bf[4];
#pragma unroll
            for (int i = 0; i < 2; i++)
                wmma::load_matrix_sync(af[i], st + (wm * 32 + i * 16) * LDA_H + kk, LDA_H);
#pragma unroll
            for (int jj = 0; jj < 4; jj++)
                wmma::load_matrix_sync(bf[jj], stB + kk * LDB_H + wn * 64 + jj * 16, LDB_H);
#pragma unroll
            for (int i = 0; i < 2; i++)
#pragma unroll
                for (int jj = 0; jj < 4; jj++)
                    wmma::mma_sync(acc.a[i][jj], af[i], bf[jj], acc.a[i][jj]);
        }
        __syncthreads();
    }
}

__device__ __forceinline__ void store_acc_smem(float* sC, AccTile& acc, int tid) {
    const int warp = tid >> 5;
    const int wm = warp & 3;
    const int wn = warp >> 2;
#pragma unroll
    for (int i = 0; i < 2; i++)
#pragma unroll
        for (int j = 0; j < 4; j++)
            wmma::store_matrix_sync(sC + (wm * 32 + i * 16) * LDC + wn * 64 + j * 16,
                                    acc.a[i][j], LDC, wmma::mem_row_major);
}

// ---------------- kernel 3: FFN1 = gelu(Xg @ W1 + b1) -> half --------------
__global__ __launch_bounds__(256, 2) void ffn1_kernel(const float* __restrict__ b1) {
    extern __shared__ __align__(16) __half smem_h[];
    const int tid = threadIdx.x;
    const int e = blockIdx.z, b = blockIdx.y >> 2, mt = blockIdx.y & 3;
    const int n0 = blockIdx.x * BN, m0 = mt * BM;
    const int be = b * E_ + e;

    const __half* A  = g_xgh + ((size_t)be * K_ + m0) * H_;
    const __half* Bg = g_w1h + (size_t)e * H_ * F_;

    AccTile acc;
#pragma unroll
    for (int i = 0; i < 2; i++)
#pragma unroll
        for (int j = 0; j < 4; j++) wmma::fill_fragment(acc.a[i][j], 0.f);

    gemm_half(A, H_, Bg, F_, n0, H_ / BK, smem_h, acc, tid);

    float* sC = (float*)smem_h;
    store_acc_smem(sC, acc, tid);
    __syncthreads();

    const float* b1p = b1 + (size_t)e * F_ + n0;
    __half* h1p = g_h1h + ((size_t)be * K_ + m0) * F_ + n0;
#pragma unroll
    for (int r = 0; r < 16; r++) {
        int c = tid + r * 256;
        int row = c >> 5;
        int col = (c & 31) * 4;
        float4 v = *(const float4*)(sC + row * LDC + col);
        float4 bb = *(const float4*)(b1p + col);
        __half2 h0 = __floats2half2_rn(gelu_tanh(v.x + bb.x), gelu_tanh(v.y + bb.y));
        __half2 h1 = __floats2half2_rn(gelu_tanh(v.z + bb.z), gelu_tanh(v.w + bb.w));
        __half2* dp = (__half2*)(h1p + (size_t)row * F_ + col);
        dp[0] = h0;
        dp[1] = h1;
    }
}

// ---------------- kernel 4: FFN2 + bias + gate + scatter-add ---------------
__global__ __launch_bounds__(256, 2) void ffn2_kernel(const float* __restrict__ b2,
                                                      float* __restrict__ out) {
    extern __shared__ __align__(16) __half smem_h[];
    const int tid = threadIdx.x;
    const int e = blockIdx.z, b = blockIdx.y >> 2, mt = blockIdx.y & 3;
    const int n0 = blockIdx.x * BN, m0 = mt * BM;
    const int be = b * E_ + e;

    const __half* A  = g_h1h + ((size_t)be * K_ + m0) * F_;
    const __half* Bg = g_w2h + (size_t)e * F_ * H_;

    AccTile acc;
#pragma unroll
    for (int i = 0; i < 2; i++)
#pragma unroll
        for (int j = 0; j < 4; j++) wmma::fill_fragment(acc.a[i][j], 0.f);

    gemm_half(A, F_, Bg, H_, n0, F_ / BK, smem_h, acc, tid);

    float* sC = (float*)smem_h;
    store_acc_smem(sC, acc, tid);
    __syncthreads();

    const int*   idxp  = g_idx  + (size_t)be * K_;
    const float* gatep = g_gate + (size_t)be * K_;
    const float* b2p   = b2 + (size_t)e * H_ + n0;
#pragma unroll
    for (int r = 0; r < 16; r++) {
        int c = tid + r * 256;
        int row = c >> 5;
        int col = (c & 31) * 4;
        float4 v = *(const float4*)(sC + row * LDC + col);
        float4 bb = *(const float4*)(b2p + col);
        float gsc = gatep[m0 + row];
        int token = idxp[m0 + row];
        float* op = out + ((size_t)b * S_ + token) * H_ + n0 + col;
        atomicAdd(op + 0, (v.x + bb.x) * gsc);
        atomicAdd(op + 1, (v.y + bb.y) * gsc);
        atomicAdd(op + 2, (v.z + bb.z) * gsc);
        atomicAdd(op + 3, (v.w + bb.w) * gsc);
    }
}

// ---------------- launch ----------------------------------------------------
extern "C" void kernel_launch(void* const* d_in, const int* in_sizes, int n_in,
                              void* d_out, int out_size) {
    const float* x  = (const float*)d_in[0];
    const float* Wg = (const float*)d_in[1];
    const float* W1 = (const float*)d_in[2];
    const float* b1 = (const float*)d_in[3];
    const float* W2 = (const float*)d_in[4];
    const float* b2 = (const float*)d_in[5];
    float* out = (float*)d_out;

    static int inited = 0;
    if (!inited) {
        cudaFuncSetAttribute(ffn1_kernel, cudaFuncAttributeMaxDynamicSharedMemorySize, SMEM_BYTES);
        cudaFuncSetAttribute(ffn2_kernel, cudaFuncAttributeMaxDynamicSharedMemorySize, SMEM_BYTES);
        inited = 1;
    }

    __half* w1h; cudaGetSymbolAddress((void**)&w1h, g_w1h);
    __half* w2h; cudaGetSymbolAddress((void**)&w2h, g_w2h);

    cudaMemsetAsync(out, 0, (size_t)B_ * S_ * H_ * sizeof(float), 0);
    gate_kernel<<<(B_ * S_) / 8, 256>>>(x, Wg);
    convert_kernel<<<(E_ * (size_t)H_ * F_) / 1024, 256>>>(W1, w1h);
    convert_kernel<<<(E_ * (size_t)F_ * H_) / 1024, 256>>>(W2, w2h);
    topk_kernel<<<B_ * E_, 1024>>>();
    gather_kernel<<<B_ * E_ * K_, 256>>>(x);
    ffn1_kernel<<<dim3(F_ / BN, (B_ * K_) / BM, E_), 256, SMEM_BYTES>>>(b1);
    ffn2_kernel<<<dim3(H_ / BN, (B_ * K_) / BM, E_), 256, SMEM_BYTES>>>(b2, out);
}